// round 4
// baseline (speedup 1.0000x reference)
#include <cuda_runtime.h>
#include <math.h>

#define DD 4096
#define NB 1184          // 148 SMs * 8 persistent blocks
#define NT 256

__device__ float g_xk[DD], g_xv[DD], g_xr[DD];
__device__ float g_k[DD], g_v[DD], g_r[DD], g_rv[DD];

__global__ void mix_kernel(const float* __restrict__ x,
                           const float* __restrict__ sxx,
                           const float* __restrict__ tmk,
                           const float* __restrict__ tmv,
                           const float* __restrict__ tmr) {
    int i = blockIdx.x * blockDim.x + threadIdx.x;  // float4 index
    if (i >= DD / 4) return;
    float4 xi = ((const float4*)x)[i];
    float4 si = ((const float4*)sxx)[i];
    float4 k = ((const float4*)tmk)[i];
    float4 v = ((const float4*)tmv)[i];
    float4 r = ((const float4*)tmr)[i];
    float4 ok, ov, orr;
    ok.x = xi.x*k.x + si.x*(1.f-k.x); ok.y = xi.y*k.y + si.y*(1.f-k.y);
    ok.z = xi.z*k.z + si.z*(1.f-k.z); ok.w = xi.w*k.w + si.w*(1.f-k.w);
    ov.x = xi.x*v.x + si.x*(1.f-v.x); ov.y = xi.y*v.y + si.y*(1.f-v.y);
    ov.z = xi.z*v.z + si.z*(1.f-v.z); ov.w = xi.w*v.w + si.w*(1.f-v.w);
    orr.x = xi.x*r.x + si.x*(1.f-r.x); orr.y = xi.y*r.y + si.y*(1.f-r.y);
    orr.z = xi.z*r.z + si.z*(1.f-r.z); orr.w = xi.w*r.w + si.w*(1.f-r.w);
    ((float4*)g_xk)[i] = ok;
    ((float4*)g_xv)[i] = ov;
    ((float4*)g_xr)[i] = orr;
}

// resolve task t in [0, 3*DD): matrix 0=key,1=val,2=rec
__device__ __forceinline__ void task_ptrs(int t, const float* wk, const float* wv,
                                          const float* wr, const float** W,
                                          const float** vec, int* m, int* row) {
    int mm = t >> 12;           // /4096
    *row = t & (DD - 1);
    *m = mm;
    *W   = (mm == 0) ? wk   : (mm == 1) ? wv   : wr;
    *vec = (mm == 0) ? g_xk : (mm == 1) ? g_xv : g_xr;
}

// persistent: each iteration computes 2 row-dot-products (8 float4 streams/thread)
__global__ void __launch_bounds__(NT) matvec3_kernel(const float* __restrict__ wk,
                                                     const float* __restrict__ wv,
                                                     const float* __restrict__ wr) {
    __shared__ float sh0[8], sh1[8];
    const int lane = threadIdx.x & 31, w = threadIdx.x >> 5;
    const int total = 3 * DD;

    for (int base = blockIdx.x * 2; base < total; base += gridDim.x * 2) {
        const float *W0, *V0, *W1, *V1;
        int m0, r0, m1, r1;
        task_ptrs(base, wk, wv, wr, &W0, &V0, &m0, &r0);
        int t1 = (base + 1 < total) ? base + 1 : base;
        task_ptrs(t1, wk, wv, wr, &W1, &V1, &m1, &r1);

        const float4* R0 = (const float4*)(W0 + (size_t)r0 * DD);
        const float4* R1 = (const float4*)(W1 + (size_t)r1 * DD);
        const float4* Vv0 = (const float4*)V0;
        const float4* Vv1 = (const float4*)V1;

        float s0 = 0.f, s1 = 0.f;
        #pragma unroll
        for (int j = 0; j < 4; j++) {
            int idx = threadIdx.x + j * NT;
            float4 a0 = __ldcs(&R0[idx]);
            float4 a1 = __ldcs(&R1[idx]);
            float4 b0 = __ldg(&Vv0[idx]);
            float4 b1 = __ldg(&Vv1[idx]);
            s0 = fmaf(a0.x, b0.x, s0); s0 = fmaf(a0.y, b0.y, s0);
            s0 = fmaf(a0.z, b0.z, s0); s0 = fmaf(a0.w, b0.w, s0);
            s1 = fmaf(a1.x, b1.x, s1); s1 = fmaf(a1.y, b1.y, s1);
            s1 = fmaf(a1.z, b1.z, s1); s1 = fmaf(a1.w, b1.w, s1);
        }
        #pragma unroll
        for (int o = 16; o; o >>= 1) {
            s0 += __shfl_xor_sync(0xffffffffu, s0, o);
            s1 += __shfl_xor_sync(0xffffffffu, s1, o);
        }
        if (lane == 0) { sh0[w] = s0; sh1[w] = s1; }
        __syncthreads();
        if (w == 0) {
            s0 = (lane < 8) ? sh0[lane] : 0.f;
            s1 = (lane < 8) ? sh1[lane] : 0.f;
            #pragma unroll
            for (int o = 4; o; o >>= 1) {
                s0 += __shfl_xor_sync(0xffffffffu, s0, o);
                s1 += __shfl_xor_sync(0xffffffffu, s1, o);
            }
            if (lane == 0) {
                if (m0 == 0) g_k[r0] = s0;
                else if (m0 == 1) g_v[r0] = s0;
                else g_r[r0] = 1.0f / (1.0f + expf(-s0));
                if (t1 != base) {
                    if (m1 == 0) g_k[r1] = s1;
                    else if (m1 == 1) g_v[r1] = s1;
                    else g_r[r1] = 1.0f / (1.0f + expf(-s1));
                }
            }
        }
        __syncthreads();
    }
}

// elementwise WKV. out: [y | x | new_aa | new_bb | new_pp]
__global__ void wkv_kernel(const float* __restrict__ x,
                           const float* __restrict__ aa,
                           const float* __restrict__ bb,
                           const float* __restrict__ pp,
                           const float* __restrict__ t_decay,
                           const float* __restrict__ t_first,
                           float* __restrict__ out) {
    int i = blockIdx.x * blockDim.x + threadIdx.x;
    if (i >= DD) return;
    float k = g_k[i], v = g_v[i], r = g_r[i];
    float ppi = pp[i], aai = aa[i], bbi = bb[i];

    float ww = t_first[i] + k;
    float p  = fmaxf(ppi, ww);
    float e1 = expf(ppi - p);
    float e2 = expf(ww - p);
    float a  = fmaf(e1, aai, e2 * v);
    float b  = fmaf(e1, bbi, e2);
    g_rv[i]  = r * (a / b);

    float ww2 = ppi + t_decay[i];
    float p2  = fmaxf(ww2, k);
    float e1b = expf(ww2 - p2);
    float e2b = expf(k - p2);

    out[DD + i]     = x[i];
    out[2 * DD + i] = fmaf(e1b, aai, e2b * v);
    out[3 * DD + i] = fmaf(e1b, bbi, e2b);
    out[4 * DD + i] = p2;
}

__global__ void __launch_bounds__(NT) matvec_out_kernel(const float* __restrict__ wo,
                                                        float* __restrict__ out) {
    __shared__ float sh0[8], sh1[8];
    const int lane = threadIdx.x & 31, w = threadIdx.x >> 5;
    const float4* Vv = (const float4*)g_rv;

    for (int base = blockIdx.x * 2; base < DD; base += gridDim.x * 2) {
        int r0 = base, r1 = base + 1;   // DD even, both valid
        const float4* R0 = (const float4*)(wo + (size_t)r0 * DD);
        const float4* R1 = (const float4*)(wo + (size_t)r1 * DD);

        float s0 = 0.f, s1 = 0.f;
        #pragma unroll
        for (int j = 0; j < 4; j++) {
            int idx = threadIdx.x + j * NT;
            float4 a0 = __ldcs(&R0[idx]);
            float4 a1 = __ldcs(&R1[idx]);
            float4 b  = __ldg(&Vv[idx]);
            s0 = fmaf(a0.x, b.x, s0); s0 = fmaf(a0.y, b.y, s0);
            s0 = fmaf(a0.z, b.z, s0); s0 = fmaf(a0.w, b.w, s0);
            s1 = fmaf(a1.x, b.x, s1); s1 = fmaf(a1.y, b.y, s1);
            s1 = fmaf(a1.z, b.z, s1); s1 = fmaf(a1.w, b.w, s1);
        }
        #pragma unroll
        for (int o = 16; o; o >>= 1) {
            s0 += __shfl_xor_sync(0xffffffffu, s0, o);
            s1 += __shfl_xor_sync(0xffffffffu, s1, o);
        }
        if (lane == 0) { sh0[w] = s0; sh1[w] = s1; }
        __syncthreads();
        if (w == 0) {
            s0 = (lane < 8) ? sh0[lane] : 0.f;
            s1 = (lane < 8) ? sh1[lane] : 0.f;
            #pragma unroll
            for (int o = 4; o; o >>= 1) {
                s0 += __shfl_xor_sync(0xffffffffu, s0, o);
                s1 += __shfl_xor_sync(0xffffffffu, s1, o);
            }
            if (lane == 0) { out[r0] = s0; out[r1] = s1; }
        }
        __syncthreads();
    }
}

extern "C" void kernel_launch(void* const* d_in, const int* in_sizes, int n_in,
                              void* d_out, int out_size) {
    const float* x       = (const float*)d_in[0];
    const float* sxx     = (const float*)d_in[1];
    const float* aa      = (const float*)d_in[2];
    const float* bb      = (const float*)d_in[3];
    const float* pp      = (const float*)d_in[4];
    const float* w_key   = (const float*)d_in[5];
    const float* w_val   = (const float*)d_in[6];
    const float* w_rec   = (const float*)d_in[7];
    const float* w_out   = (const float*)d_in[8];
    const float* t_decay = (const float*)d_in[9];
    const float* t_first = (const float*)d_in[10];
    const float* t_mix_k = (const float*)d_in[11];
    const float* t_mix_v = (const float*)d_in[12];
    const float* t_mix_r = (const float*)d_in[13];
    float* out = (float*)d_out;

    mix_kernel<<<(DD / 4 + 255) / 256, 256>>>(x, sxx, t_mix_k, t_mix_v, t_mix_r);
    matvec3_kernel<<<NB, NT>>>(w_key, w_val, w_rec);
    wkv_kernel<<<DD / 256, 256>>>(x, aa, bb, pp, t_decay, t_first, out);
    matvec_out_kernel<<<NB, NT>>>(w_out, out);
}

// round 6
// speedup vs baseline: 1.0298x; 1.0298x over previous
#include <cuda_runtime.h>
#include <math.h>

#define DD 4096
#define NT 256
#define F4_PER_THREAD 4      // DD/4/NT
#define NBX 148              // blocks per matrix (matvec3); exactly-resident
#define NBO 444              // blocks for matvec_out

__device__ float g_k[DD], g_v[DD], g_r[DD], g_rv[DD];

__device__ __forceinline__ float dot4(float4 a, float4 b) {
    float s = a.x * b.x;
    s = fmaf(a.y, b.y, s);
    s = fmaf(a.z, b.z, s);
    s = fmaf(a.w, b.w, s);
    return s;
}

// block-level reduce of one float; returns valid on tid==0
__device__ __forceinline__ float block_reduce(float s, float* sh, int lane, int w) {
    #pragma unroll
    for (int o = 16; o; o >>= 1) s += __shfl_xor_sync(0xffffffffu, s, o);
    if (lane == 0) sh[w] = s;
    __syncthreads();
    if (w == 0) {
        s = (lane < NT / 32) ? sh[lane] : 0.f;
        #pragma unroll
        for (int o = 4; o; o >>= 1) s += __shfl_xor_sync(0xffffffffu, s, o);
    }
    __syncthreads();   // sh reusable next iteration
    return s;
}

// Fused mix + 3 matvecs. grid = (NBX, 3). Each block: one matrix, b in regs,
// rows strided by NBX with next-row prefetch double-buffering.
__global__ void __launch_bounds__(NT) matvec3_kernel(
        const float* __restrict__ wk, const float* __restrict__ wv,
        const float* __restrict__ wr,
        const float* __restrict__ x, const float* __restrict__ sxx,
        const float* __restrict__ tmk, const float* __restrict__ tmv,
        const float* __restrict__ tmr) {
    __shared__ float sh[NT / 32];
    const int tid = threadIdx.x, lane = tid & 31, w = tid >> 5;
    const int m = blockIdx.y;
    const float* W  = (m == 0) ? wk  : (m == 1) ? wv  : wr;
    const float* tm = (m == 0) ? tmk : (m == 1) ? tmv : tmr;

    // b = x*t + sxx*(1-t), held in registers
    float4 b[F4_PER_THREAD];
    #pragma unroll
    for (int j = 0; j < F4_PER_THREAD; j++) {
        int i = tid + j * NT;
        float4 xi = __ldg(&((const float4*)x)[i]);
        float4 si = __ldg(&((const float4*)sxx)[i]);
        float4 ti = __ldg(&((const float4*)tm)[i]);
        b[j].x = fmaf(xi.x - si.x, ti.x, si.x);
        b[j].y = fmaf(xi.y - si.y, ti.y, si.y);
        b[j].z = fmaf(xi.z - si.z, ti.z, si.z);
        b[j].w = fmaf(xi.w - si.w, ti.w, si.w);
    }

    int r = blockIdx.x;
    float4 a[F4_PER_THREAD];
    {
        const float4* Wr = (const float4*)(W + (size_t)r * DD);
        #pragma unroll
        for (int j = 0; j < F4_PER_THREAD; j++) a[j] = __ldcs(&Wr[tid + j * NT]);
    }

    while (r < DD) {
        int rn = r + NBX;
        int rl = (rn < DD) ? rn : r;          // dummy reload on last iter
        const float4* Wn = (const float4*)(W + (size_t)rl * DD);
        float4 nx[F4_PER_THREAD];
        #pragma unroll
        for (int j = 0; j < F4_PER_THREAD; j++) nx[j] = __ldcs(&Wn[tid + j * NT]);

        float s0 = dot4(a[0], b[0]) + dot4(a[1], b[1]);
        float s1 = dot4(a[2], b[2]) + dot4(a[3], b[3]);
        float s = block_reduce(s0 + s1, sh, lane, w);
        if (tid == 0) {
            if (m == 0)      g_k[r] = s;
            else if (m == 1) g_v[r] = s;
            else             g_r[r] = 1.0f / (1.0f + expf(-s));
        }
        #pragma unroll
        for (int j = 0; j < F4_PER_THREAD; j++) a[j] = nx[j];
        r = rn;
    }
}

// elementwise WKV. out: [y | x | new_aa | new_bb | new_pp]
__global__ void wkv_kernel(const float* __restrict__ x,
                           const float* __restrict__ aa,
                           const float* __restrict__ bb,
                           const float* __restrict__ pp,
                           const float* __restrict__ t_decay,
                           const float* __restrict__ t_first,
                           float* __restrict__ out) {
    int i = blockIdx.x * blockDim.x + threadIdx.x;
    if (i >= DD) return;
    float k = g_k[i], v = g_v[i], r = g_r[i];
    float ppi = pp[i], aai = aa[i], bbi = bb[i];

    float ww = t_first[i] + k;
    float p  = fmaxf(ppi, ww);
    float e1 = expf(ppi - p);
    float e2 = expf(ww - p);
    float a  = fmaf(e1, aai, e2 * v);
    float b  = fmaf(e1, bbi, e2);
    g_rv[i]  = r * (a / b);

    float ww2 = ppi + t_decay[i];
    float p2  = fmaxf(ww2, k);
    float e1b = expf(ww2 - p2);
    float e2b = expf(k - p2);

    out[DD + i]     = x[i];
    out[2 * DD + i] = fmaf(e1b, aai, e2b * v);
    out[3 * DD + i] = fmaf(e1b, bbi, e2b);
    out[4 * DD + i] = p2;
}

// y = w_out @ g_rv. b in regs, rows strided by NBO with prefetch.
__global__ void __launch_bounds__(NT) matvec_out_kernel(
        const float* __restrict__ wo, float* __restrict__ out) {
    __shared__ float sh[NT / 32];
    const int tid = threadIdx.x, lane = tid & 31, w = tid >> 5;

    float4 b[F4_PER_THREAD];
    #pragma unroll
    for (int j = 0; j < F4_PER_THREAD; j++)
        b[j] = ((const float4*)g_rv)[tid + j * NT];

    int r = blockIdx.x;
    float4 a[F4_PER_THREAD];
    {
        const float4* Wr = (const float4*)(wo + (size_t)r * DD);
        #pragma unroll
        for (int j = 0; j < F4_PER_THREAD; j++) a[j] = __ldcs(&Wr[tid + j * NT]);
    }

    while (r < DD) {
        int rn = r + NBO;
        int rl = (rn < DD) ? rn : r;
        const float4* Wn = (const float4*)(wo + (size_t)rl * DD);
        float4 nx[F4_PER_THREAD];
        #pragma unroll
        for (int j = 0; j < F4_PER_THREAD; j++) nx[j] = __ldcs(&Wn[tid + j * NT]);

        float s0 = dot4(a[0], b[0]) + dot4(a[1], b[1]);
        float s1 = dot4(a[2], b[2]) + dot4(a[3], b[3]);
        float s = block_reduce(s0 + s1, sh, lane, w);
        if (tid == 0) out[r] = s;
        #pragma unroll
        for (int j = 0; j < F4_PER_THREAD; j++) a[j] = nx[j];
        r = rn;
    }
}

extern "C" void kernel_launch(void* const* d_in, const int* in_sizes, int n_in,
                              void* d_out, int out_size) {
    const float* x       = (const float*)d_in[0];
    const float* sxx     = (const float*)d_in[1];
    const float* aa      = (const float*)d_in[2];
    const float* bb      = (const float*)d_in[3];
    const float* pp      = (const float*)d_in[4];
    const float* w_key   = (const float*)d_in[5];
    const float* w_val   = (const float*)d_in[6];
    const float* w_rec   = (const float*)d_in[7];
    const float* w_out   = (const float*)d_in[8];
    const float* t_decay = (const float*)d_in[9];
    const float* t_first = (const float*)d_in[10];
    const float* t_mix_k = (const float*)d_in[11];
    const float* t_mix_v = (const float*)d_in[12];
    const float* t_mix_r = (const float*)d_in[13];
    float* out = (float*)d_out;

    matvec3_kernel<<<dim3(NBX, 3), NT>>>(w_key, w_val, w_rec,
                                         x, sxx, t_mix_k, t_mix_v, t_mix_r);
    wkv_kernel<<<DD / 256, 256>>>(x, aa, bb, pp, t_decay, t_first, out);
    matvec_out_kernel<<<NBO, NT>>>(w_out, out);
}

// round 8
// speedup vs baseline: 1.0699x; 1.0390x over previous
#include <cuda_runtime.h>
#include <math.h>

#define DD 4096
#define NF4 (DD / 4)         // 1024 float4 per row
#define NT 256               // 8 warps per block

__device__ float g_xk[DD], g_xv[DD], g_xr[DD];
__device__ float g_k[DD], g_v[DD], g_r[DD], g_rv[DD];

__device__ __forceinline__ float dot4(float4 a, float4 b) {
    float s = a.x * b.x;
    s = fmaf(a.y, b.y, s);
    s = fmaf(a.z, b.z, s);
    s = fmaf(a.w, b.w, s);
    return s;
}

__global__ void mix_kernel(const float* __restrict__ x,
                           const float* __restrict__ sxx,
                           const float* __restrict__ tmk,
                           const float* __restrict__ tmv,
                           const float* __restrict__ tmr) {
    int i = blockIdx.x * blockDim.x + threadIdx.x;   // float4 index
    if (i >= NF4) return;
    float4 xi = ((const float4*)x)[i];
    float4 si = ((const float4*)sxx)[i];
    float4 k = ((const float4*)tmk)[i];
    float4 v = ((const float4*)tmv)[i];
    float4 r = ((const float4*)tmr)[i];
    float4 ok, ov, orr;
    ok.x = fmaf(xi.x - si.x, k.x, si.x);  ok.y = fmaf(xi.y - si.y, k.y, si.y);
    ok.z = fmaf(xi.z - si.z, k.z, si.z);  ok.w = fmaf(xi.w - si.w, k.w, si.w);
    ov.x = fmaf(xi.x - si.x, v.x, si.x);  ov.y = fmaf(xi.y - si.y, v.y, si.y);
    ov.z = fmaf(xi.z - si.z, v.z, si.z);  ov.w = fmaf(xi.w - si.w, v.w, si.w);
    orr.x = fmaf(xi.x - si.x, r.x, si.x); orr.y = fmaf(xi.y - si.y, r.y, si.y);
    orr.z = fmaf(xi.z - si.z, r.z, si.z); orr.w = fmaf(xi.w - si.w, r.w, si.w);
    ((float4*)g_xk)[i] = ok;
    ((float4*)g_xv)[i] = ov;
    ((float4*)g_xr)[i] = orr;
}

// One warp per row. No block-level sync anywhere.
// grid = (DD/8, 3): blockIdx.x*8 + warp -> row, blockIdx.y -> matrix.
__global__ void __launch_bounds__(NT) matvec3_kernel(
        const float* __restrict__ wk, const float* __restrict__ wv,
        const float* __restrict__ wr) {
    const int lane = threadIdx.x & 31;
    const int warp = threadIdx.x >> 5;
    const int row  = blockIdx.x * 8 + warp;
    const int m    = blockIdx.y;

    const float* W = (m == 0) ? wk   : (m == 1) ? wv   : wr;
    const float* B = (m == 0) ? g_xk : (m == 1) ? g_xv : g_xr;

    const float4* A  = (const float4*)(W + (size_t)row * DD);
    const float4* Bv = (const float4*)B;

    float s = 0.f;
    #pragma unroll 4
    for (int j = lane; j < NF4; j += 32) {
        float4 a = __ldcs(&A[j]);
        float4 b = __ldg(&Bv[j]);
        s += dot4(a, b);
    }
    #pragma unroll
    for (int o = 16; o; o >>= 1) s += __shfl_xor_sync(0xffffffffu, s, o);

    if (lane == 0) {
        if (m == 0)      g_k[row] = s;
        else if (m == 1) g_v[row] = s;
        else             g_r[row] = 1.0f / (1.0f + expf(-s));
    }
}

// elementwise WKV. out: [y | x | new_aa | new_bb | new_pp]
__global__ void wkv_kernel(const float* __restrict__ x,
                           const float* __restrict__ aa,
                           const float* __restrict__ bb,
                           const float* __restrict__ pp,
                           const float* __restrict__ t_decay,
                           const float* __restrict__ t_first,
                           float* __restrict__ out) {
    int i = blockIdx.x * blockDim.x + threadIdx.x;
    if (i >= DD) return;
    float k = g_k[i], v = g_v[i], r = g_r[i];
    float ppi = pp[i], aai = aa[i], bbi = bb[i];

    float ww = t_first[i] + k;
    float p  = fmaxf(ppi, ww);
    float e1 = expf(ppi - p);
    float e2 = expf(ww - p);
    float a  = fmaf(e1, aai, e2 * v);
    float b  = fmaf(e1, bbi, e2);
    g_rv[i]  = r * (a / b);

    float ww2 = ppi + t_decay[i];
    float p2  = fmaxf(ww2, k);
    float e1b = expf(ww2 - p2);
    float e2b = expf(k - p2);

    out[DD + i]     = x[i];
    out[2 * DD + i] = fmaf(e1b, aai, e2b * v);
    out[3 * DD + i] = fmaf(e1b, bbi, e2b);
    out[4 * DD + i] = p2;
}

// y = w_out @ g_rv, one warp per row, barrier-free.
__global__ void __launch_bounds__(NT) matvec_out_kernel(
        const float* __restrict__ wo, float* __restrict__ out) {
    const int lane = threadIdx.x & 31;
    const int warp = threadIdx.x >> 5;
    const int row  = blockIdx.x * 8 + warp;

    const float4* A  = (const float4*)(wo + (size_t)row * DD);
    const float4* Bv = (const float4*)g_rv;

    float s = 0.f;
    #pragma unroll 4
    for (int j = lane; j < NF4; j += 32) {
        float4 a = __ldcs(&A[j]);
        float4 b = __ldg(&Bv[j]);
        s += dot4(a, b);
    }
    #pragma unroll
    for (int o = 16; o; o >>= 1) s += __shfl_xor_sync(0xffffffffu, s, o);

    if (lane == 0) out[row] = s;
}

extern "C" void kernel_launch(void* const* d_in, const int* in_sizes, int n_in,
                              void* d_out, int out_size) {
    const float* x       = (const float*)d_in[0];
    const float* sxx     = (const float*)d_in[1];
    const float* aa      = (const float*)d_in[2];
    const float* bb      = (const float*)d_in[3];
    const float* pp      = (const float*)d_in[4];
    const float* w_key   = (const float*)d_in[5];
    const float* w_val   = (const float*)d_in[6];
    const float* w_rec   = (const float*)d_in[7];
    const float* w_out   = (const float*)d_in[8];
    const float* t_decay = (const float*)d_in[9];
    const float* t_first = (const float*)d_in[10];
    const float* t_mix_k = (const float*)d_in[11];
    const float* t_mix_v = (const float*)d_in[12];
    const float* t_mix_r = (const float*)d_in[13];
    float* out = (float*)d_out;

    mix_kernel<<<(NF4 + 255) / 256, 256>>>(x, sxx, t_mix_k, t_mix_v, t_mix_r);
    matvec3_kernel<<<dim3(DD / 8, 3), NT>>>(w_key, w_val, w_rec);
    wkv_kernel<<<DD / 256, 256>>>(x, aa, bb, pp, t_decay, t_first, out);
    matvec_out_kernel<<<DD / 8, NT>>>(w_out, out);
}